// round 4
// baseline (speedup 1.0000x reference)
#include <cuda_runtime.h>

// diff[k] = (f[k-3] - f[k+2]) / 5 with zero-padding outside [0,n)
// change[k] = diff[k]^2 for k>=1, change[0] = 0
// out[k] = (1 - change[k]/S)^5 * f[k],  S = sum(change)

#define TPB 256
#define VPT 6                              // float4 vectors per thread
#define ELEMS_PER_BLOCK (TPB * VPT * 4)    // 6144
#define MAX_BLOCKS 16384
#define FULL 0xffffffffu

__device__ float g_part[MAX_BLOCKS];
__device__ float g_invS;

// ---------------------------------------------------------------- pass 1
__global__ __launch_bounds__(TPB) void k_pass1(const float* __restrict__ f, int n) {
    const int tid  = threadIdx.x;
    const int bid  = blockIdx.x;
    const int lane = tid & 31;
    const int base = bid * ELEMS_PER_BLOCK;
    const bool interior = (bid > 0) && (base + ELEMS_PER_BLOCK + 5 <= n);

    float acc = 0.0f;

    if (interior) {
        // ---- phase 1: batch all loads (independent -> deep MLP) ----
        float4 c[VPT];
        #pragma unroll
        for (int j = 0; j < VPT; j++) {
            const int v = base + j * (TPB * 4) + tid * 4;
            c[j] = __ldg(reinterpret_cast<const float4*>(f + v));
        }
        // edge-lane halo loads, also batched
        float em3[VPT], em2[VPT], em1[VPT], ep4[VPT], ep5[VPT];
        if (lane == 0) {
            #pragma unroll
            for (int j = 0; j < VPT; j++) {
                const int v = base + j * (TPB * 4) + tid * 4;
                em3[j] = __ldg(f + v - 3);
                em2[j] = __ldg(f + v - 2);
                em1[j] = __ldg(f + v - 1);
            }
        }
        if (lane == 31) {
            #pragma unroll
            for (int j = 0; j < VPT; j++) {
                const int v = base + j * (TPB * 4) + tid * 4;
                ep4[j] = __ldg(f + v + 4);
                ep5[j] = __ldg(f + v + 5);
            }
        }
        // ---- phase 2: shuffles + math ----
        #pragma unroll
        for (int j = 0; j < VPT; j++) {
            float m3 = __shfl_up_sync(FULL, c[j].y, 1);
            float m2 = __shfl_up_sync(FULL, c[j].z, 1);
            float m1 = __shfl_up_sync(FULL, c[j].w, 1);
            float p4 = __shfl_down_sync(FULL, c[j].x, 1);
            float p5 = __shfl_down_sync(FULL, c[j].y, 1);
            if (lane == 0)  { m3 = em3[j]; m2 = em2[j]; m1 = em1[j]; }
            if (lane == 31) { p4 = ep4[j]; p5 = ep5[j]; }
            float d0 = (m3     - c[j].z) * 0.2f;
            float d1 = (m2     - c[j].w) * 0.2f;
            float d2 = (m1     - p4    ) * 0.2f;
            float d3 = (c[j].x - p5    ) * 0.2f;
            acc += d0 * d0 + d1 * d1 + d2 * d2 + d3 * d3;
        }
    } else {
        #pragma unroll
        for (int j = 0; j < VPT; j++) {
            const int v = base + j * (TPB * 4) + tid * 4;
            if (v + 3 < n) {
                float4 c = __ldg(reinterpret_cast<const float4*>(f + v));
                float m3 = (v >= 3)     ? __ldg(f + v - 3) : 0.0f;
                float m2 = (v >= 2)     ? __ldg(f + v - 2) : 0.0f;
                float m1 = (v >= 1)     ? __ldg(f + v - 1) : 0.0f;
                float p4 = (v + 4 < n)  ? __ldg(f + v + 4) : 0.0f;
                float p5 = (v + 5 < n)  ? __ldg(f + v + 5) : 0.0f;
                float d0 = (m3  - c.z) * 0.2f;
                float d1 = (m2  - c.w) * 0.2f;
                float d2 = (m1  - p4 ) * 0.2f;
                float d3 = (c.x - p5 ) * 0.2f;
                float c0 = (v == 0) ? 0.0f : d0 * d0;
                acc += c0 + d1 * d1 + d2 * d2 + d3 * d3;
            } else if (v < n) {
                for (int k = v; k < n; k++) {
                    float l = (k >= 3)    ? __ldg(f + k - 3) : 0.0f;
                    float r = (k + 2 < n) ? __ldg(f + k + 2) : 0.0f;
                    float d = (l - r) * 0.2f;
                    if (k != 0) acc += d * d;
                }
            }
        }
    }

    #pragma unroll
    for (int o = 16; o > 0; o >>= 1)
        acc += __shfl_down_sync(FULL, acc, o);

    __shared__ float smem[TPB / 32];
    const int warp = tid >> 5;
    if (lane == 0) smem[warp] = acc;
    __syncthreads();
    if (tid == 0) {
        float b = 0.0f;
        #pragma unroll
        for (int w = 0; w < TPB / 32; w++) b += smem[w];
        g_part[bid] = b;   // plain overwrite: deterministic across graph replays
    }
}

// ---------------------------------------------------------------- sum
__global__ void k_sum(int nblocks) {
    __shared__ double smem[32];
    double acc = 0.0;
    for (int i = threadIdx.x; i < nblocks; i += blockDim.x)
        acc += (double)g_part[i];
    #pragma unroll
    for (int o = 16; o > 0; o >>= 1)
        acc += __shfl_down_sync(FULL, acc, o);
    const int lane = threadIdx.x & 31;
    const int warp = threadIdx.x >> 5;
    if (lane == 0) smem[warp] = acc;
    __syncthreads();
    if (threadIdx.x == 0) {
        double s = 0.0;
        const int nw = blockDim.x / 32;
        for (int w = 0; w < nw; w++) s += smem[w];
        g_invS = (float)(1.0 / s);
    }
}

// ---------------------------------------------------------------- pass 2
__global__ __launch_bounds__(TPB) void k_pass2(const float* __restrict__ f,
                                               float* __restrict__ out, int n) {
    const int tid  = threadIdx.x;
    const int bid  = blockIdx.x;
    const int lane = tid & 31;
    const int base = bid * ELEMS_PER_BLOCK;
    const bool interior = (bid > 0) && (base + ELEMS_PER_BLOCK + 5 <= n);
    const float invS = g_invS;

    if (interior) {
        // ---- phase 1: batch loads ----
        float4 c[VPT];
        #pragma unroll
        for (int j = 0; j < VPT; j++) {
            const int v = base + j * (TPB * 4) + tid * 4;
            c[j] = __ldg(reinterpret_cast<const float4*>(f + v));
        }
        float em3[VPT], em2[VPT], em1[VPT], ep4[VPT], ep5[VPT];
        if (lane == 0) {
            #pragma unroll
            for (int j = 0; j < VPT; j++) {
                const int v = base + j * (TPB * 4) + tid * 4;
                em3[j] = __ldg(f + v - 3);
                em2[j] = __ldg(f + v - 2);
                em1[j] = __ldg(f + v - 1);
            }
        }
        if (lane == 31) {
            #pragma unroll
            for (int j = 0; j < VPT; j++) {
                const int v = base + j * (TPB * 4) + tid * 4;
                ep4[j] = __ldg(f + v + 4);
                ep5[j] = __ldg(f + v + 5);
            }
        }
        // ---- phase 2: compute + store ----
        #pragma unroll
        for (int j = 0; j < VPT; j++) {
            const int v = base + j * (TPB * 4) + tid * 4;
            float m3 = __shfl_up_sync(FULL, c[j].y, 1);
            float m2 = __shfl_up_sync(FULL, c[j].z, 1);
            float m1 = __shfl_up_sync(FULL, c[j].w, 1);
            float p4 = __shfl_down_sync(FULL, c[j].x, 1);
            float p5 = __shfl_down_sync(FULL, c[j].y, 1);
            if (lane == 0)  { m3 = em3[j]; m2 = em2[j]; m1 = em1[j]; }
            if (lane == 31) { p4 = ep4[j]; p5 = ep5[j]; }
            float d0 = (m3     - c[j].z) * 0.2f;
            float d1 = (m2     - c[j].w) * 0.2f;
            float d2 = (m1     - p4    ) * 0.2f;
            float d3 = (c[j].x - p5    ) * 0.2f;
            float t0 = 1.0f - d0 * d0 * invS;
            float t1 = 1.0f - d1 * d1 * invS;
            float t2 = 1.0f - d2 * d2 * invS;
            float t3 = 1.0f - d3 * d3 * invS;
            float q0 = t0 * t0, q1 = t1 * t1, q2 = t2 * t2, q3 = t3 * t3;
            float4 o;
            o.x = q0 * q0 * t0 * c[j].x;
            o.y = q1 * q1 * t1 * c[j].y;
            o.z = q2 * q2 * t2 * c[j].z;
            o.w = q3 * q3 * t3 * c[j].w;
            __stcs(reinterpret_cast<float4*>(out + v), o);
        }
    } else {
        #pragma unroll
        for (int j = 0; j < VPT; j++) {
            const int v = base + j * (TPB * 4) + tid * 4;
            if (v + 3 < n) {
                float4 c = __ldg(reinterpret_cast<const float4*>(f + v));
                float m3 = (v >= 3)    ? __ldg(f + v - 3) : 0.0f;
                float m2 = (v >= 2)    ? __ldg(f + v - 2) : 0.0f;
                float m1 = (v >= 1)    ? __ldg(f + v - 1) : 0.0f;
                float p4 = (v + 4 < n) ? __ldg(f + v + 4) : 0.0f;
                float p5 = (v + 5 < n) ? __ldg(f + v + 5) : 0.0f;
                float d0 = (m3  - c.z) * 0.2f;
                float d1 = (m2  - c.w) * 0.2f;
                float d2 = (m1  - p4 ) * 0.2f;
                float d3 = (c.x - p5 ) * 0.2f;
                float c0 = (v == 0) ? 0.0f : d0 * d0 * invS;
                float t0 = 1.0f - c0;
                float t1 = 1.0f - d1 * d1 * invS;
                float t2 = 1.0f - d2 * d2 * invS;
                float t3 = 1.0f - d3 * d3 * invS;
                float q0 = t0 * t0, q1 = t1 * t1, q2 = t2 * t2, q3 = t3 * t3;
                float4 o;
                o.x = q0 * q0 * t0 * c.x;
                o.y = q1 * q1 * t1 * c.y;
                o.z = q2 * q2 * t2 * c.z;
                o.w = q3 * q3 * t3 * c.w;
                __stcs(reinterpret_cast<float4*>(out + v), o);
            } else if (v < n) {
                for (int k = v; k < n; k++) {
                    float l = (k >= 3)    ? __ldg(f + k - 3) : 0.0f;
                    float r = (k + 2 < n) ? __ldg(f + k + 2) : 0.0f;
                    float d = (l - r) * 0.2f;
                    float ch = (k == 0) ? 0.0f : d * d * invS;
                    float t = 1.0f - ch;
                    float q = t * t;
                    out[k] = q * q * t * __ldg(f + k);
                }
            }
        }
    }
}

// ---------------------------------------------------------------- launch
extern "C" void kernel_launch(void* const* d_in, const int* in_sizes, int n_in,
                              void* d_out, int out_size) {
    const float* f = (const float*)d_in[0];
    float* out = (float*)d_out;
    int n = in_sizes[0];

    int blocks = (n + ELEMS_PER_BLOCK - 1) / ELEMS_PER_BLOCK;
    if (blocks > MAX_BLOCKS) blocks = MAX_BLOCKS;

    k_pass1<<<blocks, TPB>>>(f, n);
    k_sum<<<1, 1024>>>(blocks);
    k_pass2<<<blocks, TPB>>>(f, out, n);
}

// round 5
// speedup vs baseline: 1.0164x; 1.0164x over previous
#include <cuda_runtime.h>

// diff[k] = (f[k-3] - f[k+2]) / 5 with zero-padding outside [0,n)
// change[k] = diff[k]^2 for k>=1, change[0] = 0
// out[k] = (1 - change[k]/S)^5 * f[k],  S = sum(change)
//
// Single persistent kernel: phase1 (partial sums) -> manual grid sync
// (generation-counting, monotonic counters => graph-replay-safe) -> phase2.

#define TPB 256
#define CHUNK (TPB * 4)      // 1024 elems per block-iteration (1 float4/thread)
#define GRID 592             // 148 SMs x 4 blocks: fully resident (<= 152x4 too)
#define FULL 0xffffffffu

__device__ float g_part[GRID];
__device__ float g_invS;
__device__ unsigned long long g_arrive  = 0;   // monotonic across graph replays
__device__ unsigned long long g_release = 0;   // generations completed

__global__ void __launch_bounds__(TPB, 4) k_fused(const float* __restrict__ f,
                                                  float* __restrict__ out, int n) {
    const int tid  = threadIdx.x;
    const int lane = tid & 31;
    const int warp = tid >> 5;
    const int grid = gridDim.x;
    const int nchunks = (n + CHUNK - 1) / CHUNK;

    __shared__ float  s_w[TPB / 32];
    __shared__ double s_d[TPB / 32];
    __shared__ float  s_invS;
    __shared__ int    s_last;

    // ================= phase 1: sum of change =================
    float acc = 0.0f;
    for (int ch = blockIdx.x; ch < nchunks; ch += grid) {
        const int base = ch * CHUNK;
        const int v = base + tid * 4;
        if (ch > 0 && base + CHUNK + 5 <= n) {
            // interior fast path: all halo accesses valid, k >= 1 guaranteed
            float4 c = __ldg(reinterpret_cast<const float4*>(f + v));
            float m3 = __ldg(f + v - 3);
            float m2 = __ldg(f + v - 2);
            float m1 = __ldg(f + v - 1);
            float p4 = __ldg(f + v + 4);
            float p5 = __ldg(f + v + 5);
            float d0 = (m3  - c.z) * 0.2f;
            float d1 = (m2  - c.w) * 0.2f;
            float d2 = (m1  - p4 ) * 0.2f;
            float d3 = (c.x - p5 ) * 0.2f;
            acc += d0 * d0 + d1 * d1 + d2 * d2 + d3 * d3;
        } else if (v + 3 < n) {
            float4 c = __ldg(reinterpret_cast<const float4*>(f + v));
            float m3 = (v >= 3)    ? __ldg(f + v - 3) : 0.0f;
            float m2 = (v >= 2)    ? __ldg(f + v - 2) : 0.0f;
            float m1 = (v >= 1)    ? __ldg(f + v - 1) : 0.0f;
            float p4 = (v + 4 < n) ? __ldg(f + v + 4) : 0.0f;
            float p5 = (v + 5 < n) ? __ldg(f + v + 5) : 0.0f;
            float d0 = (m3  - c.z) * 0.2f;
            float d1 = (m2  - c.w) * 0.2f;
            float d2 = (m1  - p4 ) * 0.2f;
            float d3 = (c.x - p5 ) * 0.2f;
            float c0 = (v == 0) ? 0.0f : d0 * d0;
            acc += c0 + d1 * d1 + d2 * d2 + d3 * d3;
        } else if (v < n) {
            for (int k = v; k < n; k++) {
                float l = (k >= 3)    ? __ldg(f + k - 3) : 0.0f;
                float r = (k + 2 < n) ? __ldg(f + k + 2) : 0.0f;
                float d = (l - r) * 0.2f;
                if (k != 0) acc += d * d;
            }
        }
    }

    // block reduce
    #pragma unroll
    for (int o = 16; o > 0; o >>= 1)
        acc += __shfl_down_sync(FULL, acc, o);
    if (lane == 0) s_w[warp] = acc;
    __syncthreads();

    // ================= grid sync (generation counting) =================
    if (tid == 0) {
        float b = 0.0f;
        #pragma unroll
        for (int w = 0; w < TPB / 32; w++) b += s_w[w];
        g_part[blockIdx.x] = b;
        __threadfence();
        unsigned long long ticket = atomicAdd(&g_arrive, 1ULL);
        unsigned long long gen = ticket / (unsigned long long)grid;
        int last = ((int)(ticket % (unsigned long long)grid) == grid - 1);
        s_last = last;
        if (!last) {
            while (*((volatile unsigned long long*)&g_release) < gen + 1ULL) {
                __nanosleep(64);
            }
            __threadfence();
            s_invS = *((volatile float*)&g_invS);
        }
    }
    __syncthreads();

    if (s_last) {   // block-uniform branch
        __threadfence();
        double a = 0.0;
        for (int i = tid; i < grid; i += TPB)
            a += (double)g_part[i];
        #pragma unroll
        for (int o = 16; o > 0; o >>= 1)
            a += __shfl_down_sync(FULL, a, o);
        if (lane == 0) s_d[warp] = a;
        __syncthreads();
        if (tid == 0) {
            double s = 0.0;
            #pragma unroll
            for (int w = 0; w < TPB / 32; w++) s += s_d[w];
            float inv = (float)(1.0 / s);
            s_invS = inv;
            *((volatile float*)&g_invS) = inv;
            __threadfence();
            atomicAdd(&g_release, 1ULL);
        }
        __syncthreads();
    }

    const float invS = s_invS;

    // ================= phase 2: scale + write =================
    for (int ch = blockIdx.x; ch < nchunks; ch += grid) {
        const int base = ch * CHUNK;
        const int v = base + tid * 4;
        if (ch > 0 && base + CHUNK + 5 <= n) {
            float4 c = __ldg(reinterpret_cast<const float4*>(f + v));
            float m3 = __ldg(f + v - 3);
            float m2 = __ldg(f + v - 2);
            float m1 = __ldg(f + v - 1);
            float p4 = __ldg(f + v + 4);
            float p5 = __ldg(f + v + 5);
            float d0 = (m3  - c.z) * 0.2f;
            float d1 = (m2  - c.w) * 0.2f;
            float d2 = (m1  - p4 ) * 0.2f;
            float d3 = (c.x - p5 ) * 0.2f;
            float t0 = 1.0f - d0 * d0 * invS;
            float t1 = 1.0f - d1 * d1 * invS;
            float t2 = 1.0f - d2 * d2 * invS;
            float t3 = 1.0f - d3 * d3 * invS;
            float q0 = t0 * t0, q1 = t1 * t1, q2 = t2 * t2, q3 = t3 * t3;
            float4 o;
            o.x = q0 * q0 * t0 * c.x;
            o.y = q1 * q1 * t1 * c.y;
            o.z = q2 * q2 * t2 * c.z;
            o.w = q3 * q3 * t3 * c.w;
            __stcs(reinterpret_cast<float4*>(out + v), o);
        } else if (v + 3 < n) {
            float4 c = __ldg(reinterpret_cast<const float4*>(f + v));
            float m3 = (v >= 3)    ? __ldg(f + v - 3) : 0.0f;
            float m2 = (v >= 2)    ? __ldg(f + v - 2) : 0.0f;
            float m1 = (v >= 1)    ? __ldg(f + v - 1) : 0.0f;
            float p4 = (v + 4 < n) ? __ldg(f + v + 4) : 0.0f;
            float p5 = (v + 5 < n) ? __ldg(f + v + 5) : 0.0f;
            float d0 = (m3  - c.z) * 0.2f;
            float d1 = (m2  - c.w) * 0.2f;
            float d2 = (m1  - p4 ) * 0.2f;
            float d3 = (c.x - p5 ) * 0.2f;
            float c0 = (v == 0) ? 0.0f : d0 * d0 * invS;
            float t0 = 1.0f - c0;
            float t1 = 1.0f - d1 * d1 * invS;
            float t2 = 1.0f - d2 * d2 * invS;
            float t3 = 1.0f - d3 * d3 * invS;
            float q0 = t0 * t0, q1 = t1 * t1, q2 = t2 * t2, q3 = t3 * t3;
            float4 o;
            o.x = q0 * q0 * t0 * c.x;
            o.y = q1 * q1 * t1 * c.y;
            o.z = q2 * q2 * t2 * c.z;
            o.w = q3 * q3 * t3 * c.w;
            __stcs(reinterpret_cast<float4*>(out + v), o);
        } else if (v < n) {
            for (int k = v; k < n; k++) {
                float l = (k >= 3)    ? __ldg(f + k - 3) : 0.0f;
                float r = (k + 2 < n) ? __ldg(f + k + 2) : 0.0f;
                float d = (l - r) * 0.2f;
                float ch2 = (k == 0) ? 0.0f : d * d * invS;
                float t = 1.0f - ch2;
                float q = t * t;
                out[k] = q * q * t * __ldg(f + k);
            }
        }
    }
}

// ---------------------------------------------------------------- launch
extern "C" void kernel_launch(void* const* d_in, const int* in_sizes, int n_in,
                              void* d_out, int out_size) {
    const float* f = (const float*)d_in[0];
    float* out = (float*)d_out;
    int n = in_sizes[0];

    k_fused<<<GRID, TPB>>>(f, out, n);
}

// round 6
// speedup vs baseline: 1.0550x; 1.0380x over previous
#include <cuda_runtime.h>

// diff[k] = (f[k-3] - f[k+2]) / 5 with zero-padding outside [0,n)
// change[k] = diff[k]^2 for k>=1, change[0] = 0
// out[k] = (1 - change[k]/S)^5 * f[k],  S = sum(change)

#define TPB 256
#define VPT 5                              // float4 vectors per thread (batched)
#define ELEMS_PER_BLOCK (TPB * VPT * 4)    // 5120
#define MAX_BLOCKS 16384
#define FULL 0xffffffffu

__device__ float g_part[MAX_BLOCKS];
__device__ float g_invS;

// ---------------------------------------------------------------- pass 1
__global__ void __launch_bounds__(TPB, 6) k_pass1(const float* __restrict__ f, int n) {
    const int tid  = threadIdx.x;
    const int bid  = blockIdx.x;
    const int lane = tid & 31;
    const int base = bid * ELEMS_PER_BLOCK;
    const bool interior = (bid > 0) && (base + ELEMS_PER_BLOCK + 5 <= n);

    float acc = 0.0f;

    if (interior) {
        // ---- phase A: batch the 5 main loads back-to-back (deep MLP,
        //      low register cost: just c[5]) ----
        float4 c[VPT];
        #pragma unroll
        for (int j = 0; j < VPT; j++) {
            const int v = base + j * (TPB * 4) + tid * 4;
            c[j] = __ldg(reinterpret_cast<const float4*>(f + v));
        }
        // ---- phase B: halo via shuffle; edge lanes fall back to loads
        //      that hit lines already resident in L1 ----
        #pragma unroll
        for (int j = 0; j < VPT; j++) {
            const int v = base + j * (TPB * 4) + tid * 4;
            float m3 = __shfl_up_sync(FULL, c[j].y, 1);
            float m2 = __shfl_up_sync(FULL, c[j].z, 1);
            float m1 = __shfl_up_sync(FULL, c[j].w, 1);
            float p4 = __shfl_down_sync(FULL, c[j].x, 1);
            float p5 = __shfl_down_sync(FULL, c[j].y, 1);
            if (lane == 0) {
                m3 = __ldg(f + v - 3);
                m2 = __ldg(f + v - 2);
                m1 = __ldg(f + v - 1);
            }
            if (lane == 31) {
                p4 = __ldg(f + v + 4);
                p5 = __ldg(f + v + 5);
            }
            float d0 = (m3     - c[j].z) * 0.2f;
            float d1 = (m2     - c[j].w) * 0.2f;
            float d2 = (m1     - p4    ) * 0.2f;
            float d3 = (c[j].x - p5    ) * 0.2f;
            acc += d0 * d0 + d1 * d1 + d2 * d2 + d3 * d3;
        }
    } else {
        #pragma unroll
        for (int j = 0; j < VPT; j++) {
            const int v = base + j * (TPB * 4) + tid * 4;
            if (v + 3 < n) {
                float4 c = __ldg(reinterpret_cast<const float4*>(f + v));
                float m3 = (v >= 3)     ? __ldg(f + v - 3) : 0.0f;
                float m2 = (v >= 2)     ? __ldg(f + v - 2) : 0.0f;
                float m1 = (v >= 1)     ? __ldg(f + v - 1) : 0.0f;
                float p4 = (v + 4 < n)  ? __ldg(f + v + 4) : 0.0f;
                float p5 = (v + 5 < n)  ? __ldg(f + v + 5) : 0.0f;
                float d0 = (m3  - c.z) * 0.2f;
                float d1 = (m2  - c.w) * 0.2f;
                float d2 = (m1  - p4 ) * 0.2f;
                float d3 = (c.x - p5 ) * 0.2f;
                float c0 = (v == 0) ? 0.0f : d0 * d0;
                acc += c0 + d1 * d1 + d2 * d2 + d3 * d3;
            } else if (v < n) {
                for (int k = v; k < n; k++) {
                    float l = (k >= 3)    ? __ldg(f + k - 3) : 0.0f;
                    float r = (k + 2 < n) ? __ldg(f + k + 2) : 0.0f;
                    float d = (l - r) * 0.2f;
                    if (k != 0) acc += d * d;
                }
            }
        }
    }

    #pragma unroll
    for (int o = 16; o > 0; o >>= 1)
        acc += __shfl_down_sync(FULL, acc, o);

    __shared__ float smem[TPB / 32];
    const int warp = tid >> 5;
    if (lane == 0) smem[warp] = acc;
    __syncthreads();
    if (tid == 0) {
        float b = 0.0f;
        #pragma unroll
        for (int w = 0; w < TPB / 32; w++) b += smem[w];
        g_part[bid] = b;   // plain overwrite: deterministic across graph replays
    }
}

// ---------------------------------------------------------------- sum
__global__ void k_sum(int nblocks) {
    __shared__ double smem[32];
    double acc = 0.0;
    for (int i = threadIdx.x; i < nblocks; i += blockDim.x)
        acc += (double)g_part[i];
    #pragma unroll
    for (int o = 16; o > 0; o >>= 1)
        acc += __shfl_down_sync(FULL, acc, o);
    const int lane = threadIdx.x & 31;
    const int warp = threadIdx.x >> 5;
    if (lane == 0) smem[warp] = acc;
    __syncthreads();
    if (threadIdx.x == 0) {
        double s = 0.0;
        const int nw = blockDim.x / 32;
        for (int w = 0; w < nw; w++) s += smem[w];
        g_invS = (float)(1.0 / s);
    }
}

// ---------------------------------------------------------------- pass 2
__global__ void __launch_bounds__(TPB, 6) k_pass2(const float* __restrict__ f,
                                                  float* __restrict__ out, int n) {
    const int tid  = threadIdx.x;
    const int bid  = blockIdx.x;
    const int lane = tid & 31;
    const int base = bid * ELEMS_PER_BLOCK;
    const bool interior = (bid > 0) && (base + ELEMS_PER_BLOCK + 5 <= n);
    const float invS = g_invS;

    if (interior) {
        // ---- phase A: batch loads ----
        float4 c[VPT];
        #pragma unroll
        for (int j = 0; j < VPT; j++) {
            const int v = base + j * (TPB * 4) + tid * 4;
            c[j] = __ldg(reinterpret_cast<const float4*>(f + v));
        }
        // ---- phase B: compute + store ----
        #pragma unroll
        for (int j = 0; j < VPT; j++) {
            const int v = base + j * (TPB * 4) + tid * 4;
            float m3 = __shfl_up_sync(FULL, c[j].y, 1);
            float m2 = __shfl_up_sync(FULL, c[j].z, 1);
            float m1 = __shfl_up_sync(FULL, c[j].w, 1);
            float p4 = __shfl_down_sync(FULL, c[j].x, 1);
            float p5 = __shfl_down_sync(FULL, c[j].y, 1);
            if (lane == 0) {
                m3 = __ldg(f + v - 3);
                m2 = __ldg(f + v - 2);
                m1 = __ldg(f + v - 1);
            }
            if (lane == 31) {
                p4 = __ldg(f + v + 4);
                p5 = __ldg(f + v + 5);
            }
            float d0 = (m3     - c[j].z) * 0.2f;
            float d1 = (m2     - c[j].w) * 0.2f;
            float d2 = (m1     - p4    ) * 0.2f;
            float d3 = (c[j].x - p5    ) * 0.2f;
            float t0 = 1.0f - d0 * d0 * invS;
            float t1 = 1.0f - d1 * d1 * invS;
            float t2 = 1.0f - d2 * d2 * invS;
            float t3 = 1.0f - d3 * d3 * invS;
            float q0 = t0 * t0, q1 = t1 * t1, q2 = t2 * t2, q3 = t3 * t3;
            float4 o;
            o.x = q0 * q0 * t0 * c[j].x;
            o.y = q1 * q1 * t1 * c[j].y;
            o.z = q2 * q2 * t2 * c[j].z;
            o.w = q3 * q3 * t3 * c[j].w;
            __stcs(reinterpret_cast<float4*>(out + v), o);
        }
    } else {
        #pragma unroll
        for (int j = 0; j < VPT; j++) {
            const int v = base + j * (TPB * 4) + tid * 4;
            if (v + 3 < n) {
                float4 c = __ldg(reinterpret_cast<const float4*>(f + v));
                float m3 = (v >= 3)    ? __ldg(f + v - 3) : 0.0f;
                float m2 = (v >= 2)    ? __ldg(f + v - 2) : 0.0f;
                float m1 = (v >= 1)    ? __ldg(f + v - 1) : 0.0f;
                float p4 = (v + 4 < n) ? __ldg(f + v + 4) : 0.0f;
                float p5 = (v + 5 < n) ? __ldg(f + v + 5) : 0.0f;
                float d0 = (m3  - c.z) * 0.2f;
                float d1 = (m2  - c.w) * 0.2f;
                float d2 = (m1  - p4 ) * 0.2f;
                float d3 = (c.x - p5 ) * 0.2f;
                float c0 = (v == 0) ? 0.0f : d0 * d0 * invS;
                float t0 = 1.0f - c0;
                float t1 = 1.0f - d1 * d1 * invS;
                float t2 = 1.0f - d2 * d2 * invS;
                float t3 = 1.0f - d3 * d3 * invS;
                float q0 = t0 * t0, q1 = t1 * t1, q2 = t2 * t2, q3 = t3 * t3;
                float4 o;
                o.x = q0 * q0 * t0 * c.x;
                o.y = q1 * q1 * t1 * c.y;
                o.z = q2 * q2 * t2 * c.z;
                o.w = q3 * q3 * t3 * c.w;
                __stcs(reinterpret_cast<float4*>(out + v), o);
            } else if (v < n) {
                for (int k = v; k < n; k++) {
                    float l = (k >= 3)    ? __ldg(f + k - 3) : 0.0f;
                    float r = (k + 2 < n) ? __ldg(f + k + 2) : 0.0f;
                    float d = (l - r) * 0.2f;
                    float ch = (k == 0) ? 0.0f : d * d * invS;
                    float t = 1.0f - ch;
                    float q = t * t;
                    out[k] = q * q * t * __ldg(f + k);
                }
            }
        }
    }
}

// ---------------------------------------------------------------- launch
extern "C" void kernel_launch(void* const* d_in, const int* in_sizes, int n_in,
                              void* d_out, int out_size) {
    const float* f = (const float*)d_in[0];
    float* out = (float*)d_out;
    int n = in_sizes[0];

    int blocks = (n + ELEMS_PER_BLOCK - 1) / ELEMS_PER_BLOCK;
    if (blocks > MAX_BLOCKS) blocks = MAX_BLOCKS;

    k_pass1<<<blocks, TPB>>>(f, n);
    k_sum<<<1, 1024>>>(blocks);
    k_pass2<<<blocks, TPB>>>(f, out, n);
}